// round 17
// baseline (speedup 1.0000x reference)
#include <cuda_runtime.h>
#include <cuda_bf16.h>
#include <stdint.h>

#define N_TOK 8192
#define NE    16384
#define EDIM  256
#define NTILE 128                    // codes per iteration
#define NQ    (NE / 4)               // codes per CTA (N-split by 4)
#define NIT   (NQ / NTILE)           // 32 iterations
#define ZQ_ELEMS  (N_TOK * EDIM)     // 2,097,152
#define Z_ELEMS   (N_TOK * EDIM)
#define EMB_ELEMS (NE * EDIM)

typedef unsigned long long u64;

// ---- scratch (alloc-free: __device__ globals) ----
__device__ __align__(16) float g_zn[N_TOK * EDIM];       // fp32 normalized tokens
__device__ __align__(16) float g_en[NE * EDIM];          // fp32 normalized codebook
__device__ __align__(16) int8_t g_zn8[N_TOK * EDIM];     // int8 tokens (MMA A)
__device__ __align__(16) int8_t g_en8[NE * EDIM];        // int8 codebook (MMA B)
__device__ float g_e2[NE];                               // ||en||^2
__device__ float g_sz[N_TOK];                            // token dequant scale (incl. factor 2)
__device__ float g_se[NE];                               // code dequant scale
__device__ u64 g_cand[N_TOK * 16];                       // top-4 per token per quarter
__device__ float g_loss_part[N_TOK];

__device__ __forceinline__ unsigned int fkey(float f) {
    unsigned int u = __float_as_uint(f);
    return u ^ ((unsigned int)((int)u >> 31) | 0x80000000u);
}
__device__ __forceinline__ uint32_t smem_u32(const void* p) {
    uint32_t a;
    asm("{ .reg .u64 t; cvta.to.shared.u64 t, %1; cvt.u32.u64 %0, t; }" : "=r"(a) : "l"(p));
    return a;
}
__device__ __forceinline__ void cp16(uint32_t dst, const void* src) {
    asm volatile("cp.async.cg.shared.global [%0], [%1], 16;" :: "r"(dst), "l"(src));
}
#define CP_COMMIT() asm volatile("cp.async.commit_group;" ::: "memory")
#define CP_WAIT0()  asm volatile("cp.async.wait_group 0;" ::: "memory")

__device__ __forceinline__ void ldm_x4(uint32_t* r, uint32_t addr) {
    asm volatile("ldmatrix.sync.aligned.m8n8.x4.shared.b16 {%0,%1,%2,%3}, [%4];"
                 : "=r"(r[0]), "=r"(r[1]), "=r"(r[2]), "=r"(r[3]) : "r"(addr));
}
// int8 MMA: D(s32) += A(s8,16x32) * B(s8,32x8)
__device__ __forceinline__ void mma16832(int* c, const uint32_t* a, uint32_t b0, uint32_t b1) {
    asm volatile(
        "mma.sync.aligned.m16n8k32.row.col.s32.s8.s8.s32 "
        "{%0,%1,%2,%3}, {%4,%5,%6,%7}, {%8,%9}, {%0,%1,%2,%3};"
        : "+r"(c[0]), "+r"(c[1]), "+r"(c[2]), "+r"(c[3])
        : "r"(a[0]), "r"(a[1]), "r"(a[2]), "r"(a[3]), "r"(b0), "r"(b1));
}
__device__ __forceinline__ void ins2(float& a0, int& j0, float& a1, int& j1, float s, int j) {
    if (s > a1) {
        if (s > a0) { a1 = a0; j1 = j0; a0 = s; j0 = j; }
        else        { a1 = s;  j1 = j; }
    }
}
__device__ __forceinline__ void ins4u(u64* t, u64 p) {
    if (p > t[0])      { t[3] = t[2]; t[2] = t[1]; t[1] = t[0]; t[0] = p; }
    else if (p > t[1]) { t[3] = t[2]; t[2] = t[1]; t[1] = p; }
    else if (p > t[2]) { t[3] = t[2]; t[2] = p; }
    else if (p > t[3]) { t[3] = p; }
}
__device__ __forceinline__ int8_t qscale(float v, float inv) {
    int q = __float2int_rn(v * inv);
    q = (q > 127) ? 127 : ((q < -127) ? -127 : q);
    return (int8_t)q;
}

// blocked-atom SW128 byte offset for (row, kbyte) in a 128-row x 256-byte int8 tile
__device__ __forceinline__ uint32_t tile_off(int row, int kbyte) {
    uint32_t byte = (uint32_t)(((kbyte >> 7) * 16 + (row >> 3)) * 1024 + (row & 7) * 128 + (kbyte & 127));
    return byte ^ ((byte >> 3) & 0x70);
}

// ---- smem layout for kscore (dynamic, 1024-aligned) ----
#define SM_A    0
#define SM_B0   32768
#define SM_B1   65536
#define SM_E0   98304
#define SM_E1   99328
#define SMEM_SZ 100352

// ---------------------------------------------------------------------------
// Kernel 1 (fused norms): blocks [0,16384) = codebook rows; rest = z slabs.
__global__ void knorm(const float* __restrict__ z, const float* __restrict__ emb) {
    __shared__ float tile[32][EDIM + 1];
    int tid = threadIdx.x;
    if (blockIdx.x < NE) {
        int j = blockIdx.x;
        float v = emb[(size_t)j * EDIM + tid];
        __shared__ float sm[8], sx[8];
        float s = v * v;
        #pragma unroll
        for (int o = 16; o > 0; o >>= 1) s += __shfl_xor_sync(0xFFFFFFFFu, s, o);
        if ((tid & 31) == 0) sm[tid >> 5] = s;
        __syncthreads();
        float tot = sm[0] + sm[1] + sm[2] + sm[3] + sm[4] + sm[5] + sm[6] + sm[7];
        float den = fmaxf(sqrtf(tot), 1e-12f);
        float e = v / den;
        g_en[(size_t)j * EDIM + tid] = e;
        float mx = fabsf(e);
        #pragma unroll
        for (int o = 16; o > 0; o >>= 1) mx = fmaxf(mx, __shfl_xor_sync(0xFFFFFFFFu, mx, o));
        if ((tid & 31) == 0) sx[tid >> 5] = mx;
        __syncthreads();
        float mxr = fmaxf(fmaxf(fmaxf(sx[0], sx[1]), fmaxf(sx[2], sx[3])),
                          fmaxf(fmaxf(sx[4], sx[5]), fmaxf(sx[6], sx[7])));
        mxr = fmaxf(mxr, 1e-12f);
        g_en8[(size_t)j * EDIM + tid] = qscale(e, 127.0f / mxr);
        float s2 = e * e;
        #pragma unroll
        for (int o = 16; o > 0; o >>= 1) s2 += __shfl_xor_sync(0xFFFFFFFFu, s2, o);
        if ((tid & 31) == 0) sm[tid >> 5] = s2;
        __syncthreads();
        if (tid == 0) {
            g_e2[j] = sm[0] + sm[1] + sm[2] + sm[3] + sm[4] + sm[5] + sm[6] + sm[7];
            g_se[j] = mxr / 127.0f;
        }
    } else {
        int blk = blockIdx.x - NE, b = blk >> 5, h = blk & 31;
        const float* zb = z + (size_t)b * (EDIM * 1024) + h * 32;
        for (int i = tid; i < 32 * EDIM; i += 256) {
            int c = i >> 5, w = i & 31;
            tile[w][c] = zb[c * 1024 + w];
        }
        __syncthreads();
        int warp = tid >> 5, lane = tid & 31;
        for (int s = 0; s < 4; s++) {
            int w = warp * 4 + s;
            float acc = 0.f, mx = 0.f;
            #pragma unroll
            for (int c = lane; c < EDIM; c += 32) {
                float v = tile[w][c];
                acc += v * v;
                mx = fmaxf(mx, fabsf(v));
            }
            #pragma unroll
            for (int o = 16; o > 0; o >>= 1) {
                acc += __shfl_xor_sync(0xFFFFFFFFu, acc, o);
                mx = fmaxf(mx, __shfl_xor_sync(0xFFFFFFFFu, mx, o));
            }
            float den = fmaxf(sqrtf(acc), 1e-12f);
            float mxn = fmaxf(mx / den, 1e-12f);
            float inv = 127.0f / mxn;
            int n = b * 1024 + h * 32 + w;
            if (lane == 0) g_sz[n] = 2.0f * mxn / 127.0f;
            #pragma unroll
            for (int c = lane; c < EDIM; c += 32) {
                float v = tile[w][c] / den;
                g_zn[(size_t)n * EDIM + c] = v;
                g_zn8[(size_t)n * EDIM + c] = qscale(v, inv);
            }
        }
    }
}

// ---------------------------------------------------------------------------
// Kernel 2: int8 IMMA scoring; per-thread float top-2; end-merge to top-4/quarter.
// grid (64 token-groups, 4 code-quarters), 256 threads = 8 warps, 2 CTAs/SM.
__global__ void __launch_bounds__(256, 2) kscore() {
    extern __shared__ __align__(1024) unsigned char smem[];
    uint32_t sb = smem_u32(smem);
    int tid = threadIdx.x, wid = tid >> 5, lane = tid & 31;
    int m0 = blockIdx.x * 128;
    int nbase = blockIdx.y * NQ;

    {
        const int8_t* A = g_zn8 + (size_t)m0 * EDIM;
        const int8_t* B = g_en8 + (size_t)nbase * EDIM;
        for (int q = tid; q < 2048; q += 256) {
            int r = q >> 4, kb = (q & 15) * 16;
            cp16(sb + SM_A  + tile_off(r, kb), A + (size_t)r * EDIM + kb);
            cp16(sb + SM_B0 + tile_off(r, kb), B + (size_t)r * EDIM + kb);
        }
        if (tid < 32)       cp16(sb + SM_E0 + tid * 16, g_e2 + nbase + tid * 4);
        else if (tid < 64)  cp16(sb + SM_E0 + 512 + (tid - 32) * 16, g_se + nbase + (tid - 32) * 4);
    }
    CP_COMMIT(); CP_WAIT0();
    __syncthreads();

    int gr = lane >> 2, gc = lane & 3;
    int mw = wid * 16;
    int lm_row = (lane & 15);
    int lm_koff = (lane >> 4) * 16;        // bytes

    float szr0 = g_sz[m0 + mw + gr];       // includes the 2x
    float szr1 = g_sz[m0 + mw + gr + 8];

    float a00 = -1e30f, a01 = -1e30f, a10 = -1e30f, a11 = -1e30f;
    int   j00 = 0,      j01 = 0,      j10 = 0,      j11 = 0;

    for (int i = 0; i < NIT; i++) {
        int cur = i & 1;
        if (i + 1 < NIT) {
            uint32_t bb = cur ? SM_B0 : SM_B1;
            uint32_t eb = cur ? SM_E0 : SM_E1;
            const int8_t* B = g_en8 + (size_t)(nbase + (i + 1) * NTILE) * EDIM;
            for (int q = tid; q < 2048; q += 256) {
                int r = q >> 4, kb = (q & 15) * 16;
                cp16(sb + bb + tile_off(r, kb), B + (size_t)r * EDIM + kb);
            }
            if (tid < 32)      cp16(sb + eb + tid * 16, g_e2 + nbase + (i + 1) * NTILE + tid * 4);
            else if (tid < 64) cp16(sb + eb + 512 + (tid - 32) * 16,
                                    g_se + nbase + (i + 1) * NTILE + (tid - 32) * 4);
            CP_COMMIT();
        }

        uint32_t Bb = sb + (cur ? SM_B1 : SM_B0);
        int acc[16][4];
        #pragma unroll
        for (int f = 0; f < 16; f++)
            #pragma unroll
            for (int c = 0; c < 4; c++) acc[f][c] = 0;

        #pragma unroll
        for (int ks = 0; ks < 8; ks++) {           // 8 x 32-byte k-steps = 256
            int k0 = ks * 32;
            uint32_t a[4];
            ldm_x4(a, sb + SM_A + tile_off(mw + lm_row, k0 + lm_koff));
            uint32_t bcur[4];
            ldm_x4(bcur, Bb + tile_off(lm_row, k0 + lm_koff));   // nf2 = 0
            #pragma unroll
            for (int nf2 = 0; nf2 < 8; nf2++) {
                uint32_t bnxt[4];
                if (nf2 < 7)
                    ldm_x4(bnxt, Bb + tile_off((nf2 + 1) * 16 + lm_row, k0 + lm_koff));
                mma16832(acc[nf2 * 2],     a, bcur[0], bcur[2]);
                mma16832(acc[nf2 * 2 + 1], a, bcur[1], bcur[3]);
                if (nf2 < 7) {
                    bcur[0] = bnxt[0]; bcur[1] = bnxt[1];
                    bcur[2] = bnxt[2]; bcur[3] = bnxt[3];
                }
            }
        }

        const float* e2s = (const float*)(smem + (cur ? SM_E1 : SM_E0));
        const float* ses = e2s + 128;
        int ng = nbase + i * NTILE;
        #pragma unroll
        for (int nf = 0; nf < 16; nf++) {
            int nl = nf * 8 + gc * 2;
            float e0 = e2s[nl], e1 = e2s[nl + 1];
            float f0 = ses[nl], f1 = ses[nl + 1];
            float s00 = (float)acc[nf][0] * (szr0 * f0) - e0;
            float s01 = (float)acc[nf][1] * (szr0 * f1) - e1;
            float s10 = (float)acc[nf][2] * (szr1 * f0) - e0;
            float s11 = (float)acc[nf][3] * (szr1 * f1) - e1;
            ins2(a00, j00, a01, j01, s00, ng + nl);
            ins2(a00, j00, a01, j01, s01, ng + nl + 1);
            ins2(a10, j10, a11, j11, s10, ng + nl);
            ins2(a10, j10, a11, j11, s11, ng + nl + 1);
        }

        if (i + 1 < NIT) CP_WAIT0();
        __syncthreads();
    }

    // pack once, quad-merge (lanes gc=0..3 share rows); store top-4 per quarter
    u64 q0[4], q1[4];
    q0[0] = ((u64)fkey(a00) << 32) | (unsigned int)(~(unsigned int)j00);
    q0[1] = ((u64)fkey(a01) << 32) | (unsigned int)(~(unsigned int)j01);
    q0[2] = 0; q0[3] = 0;
    q1[0] = ((u64)fkey(a10) << 32) | (unsigned int)(~(unsigned int)j10);
    q1[1] = ((u64)fkey(a11) << 32) | (unsigned int)(~(unsigned int)j11);
    q1[2] = 0; q1[3] = 0;
    #pragma unroll
    for (int off = 1; off <= 2; off <<= 1) {
        u64 in0[4], in1[4];
        #pragma unroll
        for (int s = 0; s < 4; s++) {
            in0[s] = __shfl_xor_sync(0xFFFFFFFFu, q0[s], off);
            in1[s] = __shfl_xor_sync(0xFFFFFFFFu, q1[s], off);
        }
        #pragma unroll
        for (int s = 0; s < 4; s++) { ins4u(q0, in0[s]); ins4u(q1, in1[s]); }
    }
    if (gc == 0) {
        size_t r0 = (size_t)(m0 + mw + gr) * 16 + blockIdx.y * 4;
        size_t r1 = (size_t)(m0 + mw + gr + 8) * 16 + blockIdx.y * 4;
        #pragma unroll
        for (int s = 0; s < 4; s++) { g_cand[r0 + s] = q0[s]; g_cand[r1 + s] = q1[s]; }
    }
}

// ---------------------------------------------------------------------------
// Kernel 3 (fused pick+gather): one block per token. Warp w rescores candidates
// 2w and 2w+1 in fp64; block picks argmin d (tie: smaller j); gathers z_q + loss.
__global__ void kfinal(const float* __restrict__ emb,
                       float* __restrict__ out_zq,
                       float* __restrict__ out_idx, int has_idx) {
    int n = blockIdx.x, tid = threadIdx.x;
    int warp = tid >> 5, lane = tid & 31;
    __shared__ double sd[16];
    __shared__ int sj[16];
    __shared__ int win;
    __shared__ float sl[8];

    const float* zr = g_zn + (size_t)n * EDIM;
    #pragma unroll
    for (int t = 0; t < 2; t++) {
        int slot = warp * 2 + t;
        int j = (int)(~(unsigned int)g_cand[(size_t)n * 16 + slot]);
        const float* er = g_en + (size_t)j * EDIM;
        double s = 0.0, q = 0.0;
        #pragma unroll
        for (int u = 0; u < 8; u++) {
            int c = lane * 8 + u;
            double a = (double)zr[c], x = (double)er[c];
            s += a * x; q += x * x;
        }
        #pragma unroll
        for (int o = 16; o > 0; o >>= 1) {
            s += __shfl_xor_sync(0xFFFFFFFFu, s, o);
            q += __shfl_xor_sync(0xFFFFFFFFu, q, o);
        }
        if (lane == 0) { sd[slot] = q - 2.0 * s; sj[slot] = j; }
    }
    __syncthreads();
    if (tid == 0) {
        double bd = sd[0]; int bj = sj[0];
        #pragma unroll
        for (int t = 1; t < 16; t++) {
            double d = sd[t]; int jj = sj[t];
            if (d < bd || (d == bd && jj < bj)) { bd = d; bj = jj; }
        }
        win = bj;
    }
    __syncthreads();

    int jw = win, c = tid;
    float qv = emb[(size_t)jw * EDIM + c];
    float zv = zr[c];
    float d = qv - zv;
    float ss = d * d;
    #pragma unroll
    for (int o = 16; o > 0; o >>= 1) ss += __shfl_xor_sync(0xFFFFFFFFu, ss, o);
    if (lane == 0) sl[warp] = ss;
    __syncthreads();
    if (tid == 0)
        g_loss_part[n] = sl[0] + sl[1] + sl[2] + sl[3] + sl[4] + sl[5] + sl[6] + sl[7];
    int b = n >> 10, p2 = n & 1023;
    out_zq[(size_t)b * (EDIM * 1024) + (size_t)c * 1024 + p2] = qv;
    if (c == 0 && has_idx) out_idx[n] = (float)jw;
}

// ---------------------------------------------------------------------------
// Kernel 4: loss = 2.25 * mean(sq diff).
__global__ void kloss(float* __restrict__ out_loss) {
    int tid = threadIdx.x;
    double s = 0.0;
    for (int i = tid; i < N_TOK; i += 256) s += (double)g_loss_part[i];
    __shared__ double sm[8];
    #pragma unroll
    for (int o = 16; o > 0; o >>= 1) s += __shfl_xor_sync(0xFFFFFFFFu, s, o);
    if ((tid & 31) == 0) sm[tid >> 5] = s;
    __syncthreads();
    if (tid == 0) {
        double tot = sm[0] + sm[1] + sm[2] + sm[3] + sm[4] + sm[5] + sm[6] + sm[7];
        *out_loss = (float)(2.25 * tot / (double)((size_t)N_TOK * EDIM));
    }
}

// ---------------------------------------------------------------------------
extern "C" void kernel_launch(void* const* d_in, const int* in_sizes, int n_in,
                              void* d_out, int out_size) {
    const float* z   = (const float*)d_in[0];
    const float* emb = (const float*)d_in[n_in > 1 ? 1 : 0];
    for (int i = 0; i < n_in; i++) {
        long long sz = in_sizes[i];
        if (sz == Z_ELEMS)   z   = (const float*)d_in[i];
        if (sz == EMB_ELEMS) emb = (const float*)d_in[i];
    }

    float* out = (float*)d_out;
    float* out_zq = out;
    int has_idx  = out_size >= ZQ_ELEMS + N_TOK;
    int has_loss = out_size >= ZQ_ELEMS + N_TOK + 1;
    float* out_idx  = out + ZQ_ELEMS;
    float* out_loss = out + ZQ_ELEMS + N_TOK;

    static int smem_set = 0;
    if (!smem_set) {
        cudaFuncSetAttribute(kscore, cudaFuncAttributeMaxDynamicSharedMemorySize, SMEM_SZ);
        smem_set = 1;
    }

    knorm<<<NE + 256, 256>>>(z, emb);
    kscore<<<dim3(64, 4), 256, SMEM_SZ>>>();
    kfinal<<<N_TOK, 256>>>(emb, out_zq, has_idx ? out_idx : (float*)0, has_idx);
    if (has_loss) kloss<<<1, 256>>>(out_loss);
}